// round 17
// baseline (speedup 1.0000x reference)
#include <cuda_runtime.h>

#define B_WIN 2048
#define NTOK  98
#define NHEAD 4
#define HD    32
#define C3    384
#define DIMM  128
#define NWIN  64
#define NN    (NTOK * NTOK)   // 9604
#define RPB_ROWS 507
#define NKP   49              // packed k-pairs per row

typedef unsigned int uint;

// ---------------- bf16 helpers ----------------
__device__ __forceinline__ uint pkbf(float lo, float hi) {
    uint r; asm("cvt.rn.bf16x2.f32 %0, %1, %2;" : "=r"(r) : "f"(hi), "f"(lo)); return r;
}
__device__ __forceinline__ float blo(uint p) { return __uint_as_float(p << 16); }
__device__ __forceinline__ float bhi(uint p) { return __uint_as_float(p & 0xffff0000u); }
__device__ __forceinline__ float ex2f(float x) {
    float r; asm("ex2.approx.f32 %0, %1;" : "=f"(r) : "f"(x)); return r;
}

// D += A * B  (m16n8k16, bf16 in, f32 accum)
__device__ __forceinline__ void mma16816(float* d, const uint* a, uint b0, uint b1) {
    asm("mma.sync.aligned.m16n8k16.row.col.f32.bf16.bf16.f32 "
        "{%0,%1,%2,%3}, {%4,%5,%6,%7}, {%8,%9}, {%0,%1,%2,%3};"
        : "+f"(d[0]), "+f"(d[1]), "+f"(d[2]), "+f"(d[3])
        : "r"(a[0]), "r"(a[1]), "r"(a[2]), "r"(a[3]), "r"(b0), "r"(b1));
}

// ldmatrix x4 (non-transposed / transposed)
__device__ __forceinline__ void ldm4(uint* d, uint addr) {
    asm volatile("ldmatrix.sync.aligned.m8n8.x4.shared.b16 {%0,%1,%2,%3}, [%4];"
        : "=r"(d[0]), "=r"(d[1]), "=r"(d[2]), "=r"(d[3]) : "r"(addr));
}
__device__ __forceinline__ void ldm4t(uint* d, uint addr) {
    asm volatile("ldmatrix.sync.aligned.m8n8.x4.trans.shared.b16 {%0,%1,%2,%3}, [%4];"
        : "=r"(d[0]), "=r"(d[1]), "=r"(d[2]), "=r"(d[3]) : "r"(addr));
}

#define NEGINF2 0xFF80FF80u   // bf16x2 (-inf, -inf)

// ---------------- scratch ----------------
__device__ uint g_bmh[(size_t)NWIN * NHEAD * NTOK * NKP];   // (bias+mask)*log2e bf16x2

// smem word offsets, attention phase
#define QH  0
#define QL  2240
#define KH  4480
#define KL  6720
#define VH  8960
#define VL  11200
#define QKVW 13440
// O buffer (persists): 112 rows x 132-word stride; hi words 0-63, lo words 64-127
#define OS  13440
#define OSS 132
#define SMW_TOT (OS + 112 * OSS)   // 28224 words = 112896 B
// projection W chunk overlays QKV region
#define WCLO 4352

// ---------------------------------------------------------------------------
// Kernel A: pack (bias+mask)*log2e to bf16x2 pairs along k.
// ---------------------------------------------------------------------------
__global__ void bm_kernel(const int* __restrict__ rpi,
                          const float* __restrict__ table,
                          const float* __restrict__ mask) {
    const float L2E = 1.4426950408889634f;
    int i = blockIdx.x * blockDim.x + threadIdx.x;
    if (i >= NWIN * NTOK * NKP) return;
    int w = i / (NTOK * NKP);
    int e = i - w * (NTOK * NKP);
    int q = e / NKP;
    int kp = e - q * NKP;
    int k0 = 2 * kp, k1 = 2 * kp + 1;
    int r0 = rpi[q * NTOK + k0];
    int r1 = rpi[q * NTOK + k1];
    r0 = (r0 < 0) ? 0 : (r0 >= RPB_ROWS ? RPB_ROWS - 1 : r0);
    r1 = (r1 < 0) ? 0 : (r1 >= RPB_ROWS ? RPB_ROWS - 1 : r1);
    float mk0 = mask[(size_t)w * NN + q * NTOK + k0];
    float mk1 = mask[(size_t)w * NN + q * NTOK + k1];
#pragma unroll
    for (int hh = 0; hh < NHEAD; hh++) {
        float v0 = (table[r0 * NHEAD + hh] + mk0) * L2E;
        float v1 = (table[r1 * NHEAD + hh] + mk1) * L2E;
        g_bmh[(((size_t)w * NHEAD + hh) * NTOK + q) * NKP + kp] = pkbf(v0, v1);
    }
}

// ---------------------------------------------------------------------------
// Fused: 128 threads, 4 warps, m32 per warp (2 m16 blocks; warp3 block B idle).
// K/V/W fragments shared across both m-blocks -> ~half the LDSM traffic.
// ---------------------------------------------------------------------------
__global__ __launch_bounds__(128, 2) void fused_kernel(const float* __restrict__ x,
                                                       const float* __restrict__ pw,
                                                       const float* __restrict__ pb,
                                                       float* __restrict__ out) {
    extern __shared__ uint smw[];

    const int b   = blockIdx.x;
    const int tid = threadIdx.x;
    const int lane = tid & 31;
    const int wid  = tid >> 5;
    const int g = lane >> 2;
    const int t = lane & 3;
    const int l7 = lane & 7;

    // scale folds 1/sqrt(hd) AND log2e (softmax via ex2)
    const float scale = 0.17677669529663687f * 1.4426950408889634f;
    const float* xb = x + (size_t)b * NTOK * C3;

    // attention rows: block A = wid*32 + {g, g+8}, block B = +16
    const int rA0 = wid * 32 + g,  rA1 = rA0 + 8;
    const int rB0 = rA0 + 16,      rB1 = rB0 + 8;
    const bool okA0 = rA0 < NTOK, okA1 = rA1 < NTOK;
    const bool okB0 = rB0 < NTOK, okB1 = rB1 < NTOK;
    const bool bAct = (wid < 3);   // warp3 block B = rows 112..127, all pad

    // ---- per-lane ldmatrix base addresses ----
    const uint qbaseA = (uint)__cvta_generic_to_shared(
        smw + QH + (wid * 32 + ((lane >> 3) & 1) * 8 + l7) * 20) + (lane >> 4) * 16;
    const uint qbaseB = qbaseA + 16 * 80;   // +16 rows
    const uint kbase = (uint)__cvta_generic_to_shared(
        smw + ((lane < 16) ? KH : KL) + l7 * 20) + ((lane >> 3) & 1) * 16;
    const uint vtb = (uint)__cvta_generic_to_shared(
        smw + ((lane < 16) ? VH : VL) + l7 * 20) + ((lane >> 3) & 1) * 640;
    // proj A-frag bases: block A rows wid*16.., block B rows 64+wid*16..
    const uint abaseA = (uint)__cvta_generic_to_shared(
        smw + OS + (wid * 16 + ((lane >> 3) & 1) * 8 + l7) * OSS) + (lane >> 4) * 16;
    const uint abaseB = abaseA + 64 * OSS * 4;

    // ---- targeted zeroing: QKV pad rows 98-111 (6 buffers) + Os pad rows ----
    for (int i = tid; i < 6 * 14 * 20; i += 128) {
        int buf = i / 280, rem = i - buf * 280;
        smw[buf * 2240 + 98 * 20 + rem] = 0u;
    }
    for (int i = tid; i < 14 * OSS; i += 128)
        smw[OS + 98 * OSS + i] = 0u;
    __syncthreads();

#pragma unroll
    for (int h = 0; h < NHEAD; h++) {
        // ---- load + split Q(scaled), K, V to bf16 hi/lo ----
        for (int i = tid; i < NTOK * 8; i += 128) {
            int q = i >> 3, dp4 = i & 7;
            const float4* base = (const float4*)(xb + q * C3 + h * HD) + dp4;
            float4 qv = base[0];
            qv.x *= scale; qv.y *= scale; qv.z *= scale; qv.w *= scale;
            uint h0 = pkbf(qv.x, qv.y), h1 = pkbf(qv.z, qv.w);
            *(uint2*)(smw + QH + q * 20 + 2 * dp4) = make_uint2(h0, h1);
            *(uint2*)(smw + QL + q * 20 + 2 * dp4) = make_uint2(
                pkbf(qv.x - blo(h0), qv.y - bhi(h0)),
                pkbf(qv.z - blo(h1), qv.w - bhi(h1)));
            float4 kv = base[DIMM / 4];
            uint k0 = pkbf(kv.x, kv.y), k1 = pkbf(kv.z, kv.w);
            *(uint2*)(smw + KH + q * 20 + 2 * dp4) = make_uint2(k0, k1);
            *(uint2*)(smw + KL + q * 20 + 2 * dp4) = make_uint2(
                pkbf(kv.x - blo(k0), kv.y - bhi(k0)),
                pkbf(kv.z - blo(k1), kv.w - bhi(k1)));
            float4 vv = base[2 * DIMM / 4];
            uint v0 = pkbf(vv.x, vv.y), v1 = pkbf(vv.z, vv.w);
            *(uint2*)(smw + VH + q * 20 + 2 * dp4) = make_uint2(v0, v1);
            *(uint2*)(smw + VL + q * 20 + 2 * dp4) = make_uint2(
                pkbf(vv.x - blo(v0), vv.y - bhi(v0)),
                pkbf(vv.z - blo(v1), vv.w - bhi(v1)));
        }
        __syncthreads();

        // ---- Q fragments hoisted (hi+lo, both blocks, both k-steps) ----
        uint qfhA[2][4], qflA[2][4], qfhB[2][4], qflB[2][4];
#pragma unroll
        for (int s = 0; s < 2; s++) {
            ldm4(qfhA[s], qbaseA + s * 32);
            ldm4(qflA[s], qbaseA + 8960 + s * 32);
            if (bAct) {
                ldm4(qfhB[s], qbaseB + s * 32);
                ldm4(qflB[s], qbaseB + 8960 + s * 32);
            }
        }

        const uint* bmp = g_bmh + ((size_t)(b & (NWIN - 1)) * NHEAD + h) * NTOK * NKP;
        float sA0 = 0.0f, sA1 = 0.0f, sB0 = 0.0f, sB1 = 0.0f;
        float OhA[16], OhB[16];
#pragma unroll
        for (int j = 0; j < 16; j++) { OhA[j] = 0.0f; OhB[j] = 0.0f; }

        // bias prefetch (chunk 0); layout bw[row(4)][tile(2)]
        uint bw[8];
#pragma unroll
        for (int u = 0; u < 2; u++) {
            bool cok = (u * 8 + 2 * t) < NTOK;
            bw[u]     = (okA0 && cok) ? __ldg(bmp + rA0 * NKP + u * 4 + t) : NEGINF2;
            bw[2 + u] = (okA1 && cok) ? __ldg(bmp + rA1 * NKP + u * 4 + t) : NEGINF2;
            bw[4 + u] = (okB0 && cok) ? __ldg(bmp + rB0 * NKP + u * 4 + t) : NEGINF2;
            bw[6 + u] = (okB1 && cok) ? __ldg(bmp + rB1 * NKP + u * 4 + t) : NEGINF2;
        }

        // ---- stream over k16 chunks ----
#pragma unroll
        for (int c = 0; c < 7; c++) {
            uint bwn[8];
            if (c < 6) {
#pragma unroll
                for (int u = 0; u < 2; u++) {
                    int nt = 2 * (c + 1) + u;
                    bool cok = (nt * 8 + 2 * t) < NTOK;
                    bwn[u]     = (okA0 && cok) ? __ldg(bmp + rA0 * NKP + nt * 4 + t) : NEGINF2;
                    bwn[2 + u] = (okA1 && cok) ? __ldg(bmp + rA1 * NKP + nt * 4 + t) : NEGINF2;
                    bwn[4 + u] = (okB0 && cok) ? __ldg(bmp + rB0 * NKP + nt * 4 + t) : NEGINF2;
                    bwn[6 + u] = (okB1 && cok) ? __ldg(bmp + rB1 * NKP + nt * 4 + t) : NEGINF2;
                }
            }

            float SpA[2][4], SpB[2][4];
#pragma unroll
            for (int u = 0; u < 2; u++)
#pragma unroll
                for (int j = 0; j < 4; j++) { SpA[u][j] = 0.0f; SpB[u][j] = 0.0f; }

#pragma unroll
            for (int s = 0; s < 2; s++) {
                uint kf0[4], kf1[4];
                ldm4(kf0, kbase + (2 * c) * 640 + s * 32);
                ldm4(kf1, kbase + (2 * c + 1) * 640 + s * 32);
                // hi*hi
                mma16816(SpA[0], qfhA[s], kf0[0], kf0[1]);
                mma16816(SpA[1], qfhA[s], kf1[0], kf1[1]);
                if (bAct) {
                    mma16816(SpB[0], qfhB[s], kf0[0], kf0[1]);
                    mma16816(SpB[1], qfhB[s], kf1[0], kf1[1]);
                }
                // hi*lo
                mma16816(SpA[0], qfhA[s], kf0[2], kf0[3]);
                mma16816(SpA[1], qfhA[s], kf1[2], kf1[3]);
                if (bAct) {
                    mma16816(SpB[0], qfhB[s], kf0[2], kf0[3]);
                    mma16816(SpB[1], qfhB[s], kf1[2], kf1[3]);
                }
                // lo*hi
                mma16816(SpA[0], qflA[s], kf0[0], kf0[1]);
                mma16816(SpA[1], qflA[s], kf1[0], kf1[1]);
                if (bAct) {
                    mma16816(SpB[0], qflB[s], kf0[0], kf0[1]);
                    mma16816(SpB[1], qflB[s], kf1[0], kf1[1]);
                }
            }

            // ---- bias add + ex2 ----
#pragma unroll
            for (int u = 0; u < 2; u++) {
                SpA[u][0] = ex2f(SpA[u][0] + blo(bw[u]));     sA0 += SpA[u][0];
                SpA[u][1] = ex2f(SpA[u][1] + bhi(bw[u]));     sA0 += SpA[u][1];
                SpA[u][2] = ex2f(SpA[u][2] + blo(bw[2 + u])); sA1 += SpA[u][2];
                SpA[u][3] = ex2f(SpA[u][3] + bhi(bw[2 + u])); sA1 += SpA[u][3];
                SpB[u][0] = ex2f(SpB[u][0] + blo(bw[4 + u])); sB0 += SpB[u][0];
                SpB[u][1] = ex2f(SpB[u][1] + bhi(bw[4 + u])); sB0 += SpB[u][1];
                SpB[u][2] = ex2f(SpB[u][2] + blo(bw[6 + u])); sB1 += SpB[u][2];
                SpB[u][3] = ex2f(SpB[u][3] + bhi(bw[6 + u])); sB1 += SpB[u][3];
            }
#pragma unroll
            for (int j = 0; j < 8; j++) bw[j] = bwn[j];

            // ---- pack P (both blocks) ----
            uint paA[4], plA[4], paB[4], plB[4];
            paA[0] = pkbf(SpA[0][0], SpA[0][1]);
            plA[0] = pkbf(SpA[0][0] - blo(paA[0]), SpA[0][1] - bhi(paA[0]));
            paA[1] = pkbf(SpA[0][2], SpA[0][3]);
            plA[1] = pkbf(SpA[0][2] - blo(paA[1]), SpA[0][3] - bhi(paA[1]));
            paA[2] = pkbf(SpA[1][0], SpA[1][1]);
            plA[2] = pkbf(SpA[1][0] - blo(paA[2]), SpA[1][1] - bhi(paA[2]));
            paA[3] = pkbf(SpA[1][2], SpA[1][3]);
            plA[3] = pkbf(SpA[1][2] - blo(paA[3]), SpA[1][3] - bhi(paA[3]));
            paB[0] = pkbf(SpB[0][0], SpB[0][1]);
            plB[0] = pkbf(SpB[0][0] - blo(paB[0]), SpB[0][1] - bhi(paB[0]));
            paB[1] = pkbf(SpB[0][2], SpB[0][3]);
            plB[1] = pkbf(SpB[0][2] - blo(paB[1]), SpB[0][3] - bhi(paB[1]));
            paB[2] = pkbf(SpB[1][0], SpB[1][1]);
            plB[2] = pkbf(SpB[1][0] - blo(paB[2]), SpB[1][1] - bhi(paB[2]));
            paB[3] = pkbf(SpB[1][2], SpB[1][3]);
            plB[3] = pkbf(SpB[1][2] - blo(paB[3]), SpB[1][3] - bhi(paB[3]));

            // ---- PV: V fragments shared across blocks ----
            uint vf[4][4];
#pragma unroll
            for (int nt = 0; nt < 4; nt++)
                ldm4t(vf[nt], vtb + c * 1280 + nt * 16);
#pragma unroll
            for (int nt = 0; nt < 4; nt++) {
                mma16816(&OhA[4 * nt], paA, vf[nt][0], vf[nt][1]);
                if (bAct) mma16816(&OhB[4 * nt], paB, vf[nt][0], vf[nt][1]);
            }
#pragma unroll
            for (int nt = 0; nt < 4; nt++) {
                mma16816(&OhA[4 * nt], paA, vf[nt][2], vf[nt][3]);
                if (bAct) mma16816(&OhB[4 * nt], paB, vf[nt][2], vf[nt][3]);
            }
#pragma unroll
            for (int nt = 0; nt < 4; nt++) {
                mma16816(&OhA[4 * nt], plA, vf[nt][0], vf[nt][1]);
                if (bAct) mma16816(&OhB[4 * nt], plB, vf[nt][0], vf[nt][1]);
            }
        }

        // ---- normalize + store O to smem (bf16 hi/lo) ----
        sA0 += __shfl_xor_sync(0xffffffffu, sA0, 1);
        sA0 += __shfl_xor_sync(0xffffffffu, sA0, 2);
        sA1 += __shfl_xor_sync(0xffffffffu, sA1, 1);
        sA1 += __shfl_xor_sync(0xffffffffu, sA1, 2);
        sB0 += __shfl_xor_sync(0xffffffffu, sB0, 1);
        sB0 += __shfl_xor_sync(0xffffffffu, sB0, 2);
        sB1 += __shfl_xor_sync(0xffffffffu, sB1, 1);
        sB1 += __shfl_xor_sync(0xffffffffu, sB1, 2);
        float iA0 = __frcp_rn(sA0), iA1 = __frcp_rn(sA1);
        float iB0 = __frcp_rn(sB0), iB1 = __frcp_rn(sB1);

#pragma unroll
        for (int nt = 0; nt < 4; nt++) {
            int w = 16 * h + 4 * nt + t;
            if (okA0) {
                float f0 = OhA[4 * nt + 0] * iA0, f1 = OhA[4 * nt + 1] * iA0;
                uint hw_ = pkbf(f0, f1);
                smw[OS + rA0 * OSS + w]      = hw_;
                smw[OS + rA0 * OSS + 64 + w] = pkbf(f0 - blo(hw_), f1 - bhi(hw_));
            }
            if (okA1) {
                float f2 = OhA[4 * nt + 2] * iA1, f3 = OhA[4 * nt + 3] * iA1;
                uint hw_ = pkbf(f2, f3);
                smw[OS + rA1 * OSS + w]      = hw_;
                smw[OS + rA1 * OSS + 64 + w] = pkbf(f2 - blo(hw_), f3 - bhi(hw_));
            }
            if (okB0) {
                float f0 = OhB[4 * nt + 0] * iB0, f1 = OhB[4 * nt + 1] * iB0;
                uint hw_ = pkbf(f0, f1);
                smw[OS + rB0 * OSS + w]      = hw_;
                smw[OS + rB0 * OSS + 64 + w] = pkbf(f0 - blo(hw_), f1 - bhi(hw_));
            }
            if (okB1) {
                float f2 = OhB[4 * nt + 2] * iB1, f3 = OhB[4 * nt + 3] * iB1;
                uint hw_ = pkbf(f2, f3);
                smw[OS + rB1 * OSS + w]      = hw_;
                smw[OS + rB1 * OSS + 64 + w] = pkbf(f2 - blo(hw_), f3 - bhi(hw_));
            }
        }
        __syncthreads();   // compute done before next head overwrites QKV
    }

    // ================= projection phase =================
    // proj rows: block A = wid*16 + {g,g+8}; block B = 64 + wid*16 + {g,g+8}
    const int pA0 = wid * 16 + g, pA1 = pA0 + 8;
    const int pB0 = pA0 + 64,     pB1 = pB0 + 8;
    const bool pokA0 = pA0 < NTOK, pokA1 = pA1 < NTOK;
    const bool pokB0 = pB0 < NTOK, pokB1 = pB1 < NTOK;
    const bool pAct = (wid < 3);   // warp3 block B rows 112-127: skip

    const uint wcb = (uint)__cvta_generic_to_shared(
        smw + ((lane < 16) ? 0 : WCLO) + l7 * 68) + ((lane >> 3) & 1) * 16;

#pragma unroll
    for (int c2 = 0; c2 < 2; c2++) {
        for (int i = tid; i < 2048; i += 128) {
            int j = i >> 5, dp4 = i & 31;
            float4 w = *((const float4*)(pw + (size_t)(64 * c2 + j) * DIMM) + dp4);
            uint h0 = pkbf(w.x, w.y), h1 = pkbf(w.z, w.w);
            *(uint2*)(smw + j * 68 + 2 * dp4) = make_uint2(h0, h1);
            *(uint2*)(smw + WCLO + j * 68 + 2 * dp4) = make_uint2(
                pkbf(w.x - blo(h0), w.y - bhi(h0)),
                pkbf(w.z - blo(h1), w.w - bhi(h1)));
        }
        __syncthreads();

        float RA[8][4], RB[8][4];
#pragma unroll
        for (int i = 0; i < 8; i++)
#pragma unroll
            for (int j = 0; j < 4; j++) { RA[i][j] = 0.0f; RB[i][j] = 0.0f; }

#pragma unroll
        for (int s = 0; s < 8; s++) {
            uint ahA[4], alA[4], ahB[4], alB[4];
            ldm4(ahA, abaseA + s * 32);
            ldm4(alA, abaseA + 256 + s * 32);
            if (pAct) {
                ldm4(ahB, abaseB + s * 32);
                ldm4(alB, abaseB + 256 + s * 32);
            }
#pragma unroll
            for (int i = 0; i < 8; i++) {
                uint wf[4];
                ldm4(wf, wcb + i * 2176 + s * 32);
                mma16816(RA[i], ahA, wf[0], wf[1]);
                if (pAct) mma16816(RB[i], ahB, wf[0], wf[1]);
                mma16816(RA[i], ahA, wf[2], wf[3]);
                if (pAct) mma16816(RB[i], ahB, wf[2], wf[3]);
                mma16816(RA[i], alA, wf[0], wf[1]);
                if (pAct) mma16816(RB[i], alB, wf[0], wf[1]);
            }
        }

#pragma unroll
        for (int i = 0; i < 8; i++) {
            int c0 = 64 * c2 + 8 * i + 2 * t;
            float2 bb = __ldg((const float2*)(pb + c0));
            if (pokA0) {
                float2 o = { RA[i][0] + bb.x, RA[i][1] + bb.y };
                *(float2*)(out + ((size_t)b * NTOK + pA0) * DIMM + c0) = o;
            }
            if (pokA1) {
                float2 o = { RA[i][2] + bb.x, RA[i][3] + bb.y };
                *(float2*)(out + ((size_t)b * NTOK + pA1) * DIMM + c0) = o;
            }
            if (pAct && pokB0) {
                float2 o = { RB[i][0] + bb.x, RB[i][1] + bb.y };
                *(float2*)(out + ((size_t)b * NTOK + pB0) * DIMM + c0) = o;
            }
            if (pAct && pokB1) {
                float2 o = { RB[i][2] + bb.x, RB[i][3] + bb.y };
                *(float2*)(out + ((size_t)b * NTOK + pB1) * DIMM + c0) = o;
            }
        }
        __syncthreads();
    }
}

// ---------------------------------------------------------------------------
extern "C" void kernel_launch(void* const* d_in, const int* in_sizes, int n_in,
                              void* d_out, int out_size) {
    const float* x     = (const float*)d_in[0];
    const int*   rpi   = (const int*)d_in[1];      // int32 on the wire
    const float* mask  = (const float*)d_in[2];
    const float* table = (const float*)d_in[3];
    const float* pw    = (const float*)d_in[4];
    const float* pb    = (const float*)d_in[5];
    float*       out   = (float*)d_out;

    const int smem_fused = SMW_TOT * 4;   // 112896 B
    cudaFuncSetAttribute(fused_kernel, cudaFuncAttributeMaxDynamicSharedMemorySize, smem_fused);

    bm_kernel<<<(NWIN * NTOK * NKP + 255) / 256, 256>>>(rpi, table, mask);
    fused_kernel<<<B_WIN, 128, smem_fused>>>(x, pw, pb, out);
}